// round 11
// baseline (speedup 1.0000x reference)
#include <cuda_runtime.h>
#include <cstdint>

#define N_NODES 50000
#define HIDDEN  64
#define INDIM   512
#define OUTDIM  40

// Scratch (device globals)
__device__ __align__(16) float g_hs[N_NODES * HIDDEN];    // dinv[i] * h[i]
__device__ __align__(16) float g_agg[N_NODES * HIDDEN];   // aggregated messages
__device__ __align__(16) float g_deg[N_NODES];
__device__ __align__(16) float g_dinv[N_NODES];

// ---------------------------------------------------------------------------
// Degree: deg[i] = 1 (self loop) + #edges with dst==i
// ---------------------------------------------------------------------------
__global__ void init_deg_kernel(int n) {
    int i = blockIdx.x * blockDim.x + threadIdx.x;
    if (i < n) g_deg[i] = 1.0f;
}

__global__ void deg_accum_kernel(const int* __restrict__ dst, int E, int n) {
    int e = blockIdx.x * blockDim.x + threadIdx.x;
    if (e < E) {
        int d = dst[e];
        if ((unsigned)d < (unsigned)n) atomicAdd(&g_deg[d], 1.0f);
    }
}

// ---------------------------------------------------------------------------
// GEMM1 (tensor cores, tf32): h[n,64] = X[n,512] @ W1[512,64]
// Software-pipelined: prefetch tile k+1 into registers while computing tile k.
// Fused epilogue: d = rsqrt(deg[row]); hs = d*h; agg = d*hs; dinv[row] = d.
// ---------------------------------------------------------------------------
__device__ __forceinline__ uint32_t f2tf32(float f) {
    uint32_t r;
    asm("cvt.rna.tf32.f32 %0, %1;" : "=r"(r) : "f"(f));
    return r;
}
__device__ __forceinline__ uint4 cvt4(float4 v) {
    return make_uint4(f2tf32(v.x), f2tf32(v.y), f2tf32(v.z), f2tf32(v.w));
}

#define XS_STRIDE 36
#define WS_STRIDE 72

__global__ __launch_bounds__(256) void gemm1_mma_kernel(
    const float* __restrict__ X, const float* __restrict__ W, int n)
{
    __shared__ uint32_t Xs[128 * XS_STRIDE];
    __shared__ uint32_t Ws[32 * WS_STRIDE];

    const int tid  = threadIdx.x;
    const int lane = tid & 31;
    const int wid  = tid >> 5;
    const int gid  = lane >> 2;
    const int tig  = lane & 3;
    const int wrow = wid * 16;
    const int row0 = blockIdx.x * 128;

    // Per-thread load coordinates (fixed across iterations)
    int xr[4], xq[4];
    #pragma unroll
    for (int t = 0; t < 4; t++) {
        int s = t * 256 + tid;
        xr[t] = s >> 3; xq[t] = s & 7;
    }
    int wk[2], wq[2];
    #pragma unroll
    for (int t = 0; t < 2; t++) {
        int s = t * 256 + tid;
        wk[t] = s >> 4; wq[t] = s & 15;
    }

    float4 xv[4], wv[2];
    // Prologue: load tile k0=0
    #pragma unroll
    for (int t = 0; t < 4; t++) {
        int rr = row0 + xr[t]; if (rr >= n) rr = n - 1;
        xv[t] = *(const float4*)(X + (size_t)rr * INDIM + xq[t] * 4);
    }
    #pragma unroll
    for (int t = 0; t < 2; t++)
        wv[t] = *(const float4*)(W + (size_t)wk[t] * HIDDEN + wq[t] * 4);

    float acc[8][4] = {};

    for (int k0 = 0; k0 < INDIM; k0 += 32) {
        // Store current tile (convert to tf32, vectorized STS.128)
        #pragma unroll
        for (int t = 0; t < 4; t++)
            *(uint4*)(Xs + xr[t] * XS_STRIDE + xq[t] * 4) = cvt4(xv[t]);
        #pragma unroll
        for (int t = 0; t < 2; t++)
            *(uint4*)(Ws + wk[t] * WS_STRIDE + wq[t] * 4) = cvt4(wv[t]);
        __syncthreads();

        // Prefetch next tile (LDG latency hidden behind compute below)
        int k1 = k0 + 32;
        if (k1 < INDIM) {
            #pragma unroll
            for (int t = 0; t < 4; t++) {
                int rr = row0 + xr[t]; if (rr >= n) rr = n - 1;
                xv[t] = *(const float4*)(X + (size_t)rr * INDIM + k1 + xq[t] * 4);
            }
            #pragma unroll
            for (int t = 0; t < 2; t++)
                wv[t] = *(const float4*)(W + (size_t)(k1 + wk[t]) * HIDDEN + wq[t] * 4);
        }

        // Compute on tile k0
        #pragma unroll
        for (int kk = 0; kk < 32; kk += 8) {
            uint32_t a0 = Xs[(wrow + gid) * XS_STRIDE + kk + tig];
            uint32_t a1 = Xs[(wrow + gid + 8) * XS_STRIDE + kk + tig];
            uint32_t a2 = Xs[(wrow + gid) * XS_STRIDE + kk + tig + 4];
            uint32_t a3 = Xs[(wrow + gid + 8) * XS_STRIDE + kk + tig + 4];
            #pragma unroll
            for (int nb = 0; nb < 8; nb++) {
                uint32_t b0 = Ws[(kk + tig) * WS_STRIDE + nb * 8 + gid];
                uint32_t b1 = Ws[(kk + tig + 4) * WS_STRIDE + nb * 8 + gid];
                asm volatile(
                    "mma.sync.aligned.m16n8k8.row.col.f32.tf32.tf32.f32 "
                    "{%0,%1,%2,%3}, {%4,%5,%6,%7}, {%8,%9}, {%0,%1,%2,%3};"
                    : "+f"(acc[nb][0]), "+f"(acc[nb][1]),
                      "+f"(acc[nb][2]), "+f"(acc[nb][3])
                    : "r"(a0), "r"(a1), "r"(a2), "r"(a3), "r"(b0), "r"(b1));
            }
        }
        __syncthreads();
    }

    // Fused epilogue
    const int rA = row0 + wrow + gid;
    const int rB = rA + 8;
    float dA = (rA < n) ? rsqrtf(g_deg[rA]) : 0.f;
    float dB = (rB < n) ? rsqrtf(g_deg[rB]) : 0.f;
    if (tig == 0) {
        if (rA < n) g_dinv[rA] = dA;
        if (rB < n) g_dinv[rB] = dB;
    }
    #pragma unroll
    for (int nb = 0; nb < 8; nb++) {
        int col = nb * 8 + 2 * tig;
        if (rA < n) {
            float h0 = dA * acc[nb][0], h1 = dA * acc[nb][1];
            *(float2*)(g_hs  + (size_t)rA * HIDDEN + col) = make_float2(h0, h1);
            *(float2*)(g_agg + (size_t)rA * HIDDEN + col) =
                make_float2(dA * h0, dA * h1);
        }
        if (rB < n) {
            float h2 = dB * acc[nb][2], h3 = dB * acc[nb][3];
            *(float2*)(g_hs  + (size_t)rB * HIDDEN + col) = make_float2(h2, h3);
            *(float2*)(g_agg + (size_t)rB * HIDDEN + col) =
                make_float2(dB * h2, dB * h3);
        }
    }
}

// ---------------------------------------------------------------------------
// Edge scatter: agg[dst,:] += dinv[dst] * hs[src,:]
// 4 threads per edge, 4 float4 lanes each (q, q+4, q+8, q+12) for 4x MLP.
// ---------------------------------------------------------------------------
__device__ __forceinline__ void red_add_v4(float* addr, float4 v) {
    asm volatile("red.global.add.v4.f32 [%0], {%1, %2, %3, %4};"
                 :: "l"(__cvta_generic_to_global(addr)),
                    "f"(v.x), "f"(v.y), "f"(v.z), "f"(v.w)
                 : "memory");
}

__global__ __launch_bounds__(256) void scatter_kernel(
    const int* __restrict__ src, const int* __restrict__ dst, int E, int n)
{
    int idx = blockIdx.x * blockDim.x + threadIdx.x;
    if (idx >= E * 4) return;
    int e = idx >> 2, q = idx & 3;
    int s = __ldg(src + e);
    int d = __ldg(dst + e);
    if ((unsigned)s >= (unsigned)n || (unsigned)d >= (unsigned)n) return;
    float coef = g_dinv[d];

    // Four independent gathers (lanes q, q+4, q+8, q+12) -> 4x MLP
    const float4* hsrc = (const float4*)g_hs + s * 16;
    float4 v0 = __ldg(hsrc + q);
    float4 v1 = __ldg(hsrc + q + 4);
    float4 v2 = __ldg(hsrc + q + 8);
    float4 v3 = __ldg(hsrc + q + 12);
    v0.x *= coef; v0.y *= coef; v0.z *= coef; v0.w *= coef;
    v1.x *= coef; v1.y *= coef; v1.z *= coef; v1.w *= coef;
    v2.x *= coef; v2.y *= coef; v2.z *= coef; v2.w *= coef;
    v3.x *= coef; v3.y *= coef; v3.z *= coef; v3.w *= coef;
    float* base = g_agg + (size_t)d * HIDDEN;
    red_add_v4(base + q * 4, v0);
    red_add_v4(base + (q + 4) * 4, v1);
    red_add_v4(base + (q + 8) * 4, v2);
    red_add_v4(base + (q + 12) * 4, v3);
}

// ---------------------------------------------------------------------------
// GEMM2: out[n,40] = relu(agg + b1) @ Wfc^T + bfc
// ---------------------------------------------------------------------------
__global__ __launch_bounds__(240) void gemm2_kernel(
    const float* __restrict__ b1, const float* __restrict__ Wfc,
    const float* __restrict__ bfc, float* __restrict__ out, int n)
{
    __shared__ float hs[24 * 68];
    __shared__ float Wt[64 * 40];
    __shared__ float bfs[40];

    const int tx = threadIdx.x;     // 0..9
    const int ty = threadIdx.y;     // 0..23
    const int tid = ty * 10 + tx;

    for (int idx = tid; idx < 64 * 40; idx += 240) {
        int o = idx % 40, j = idx / 40;
        Wt[j * 40 + o] = Wfc[o * 64 + j];
    }
    if (tid < 40) bfs[tid] = bfc[tid];

    const int row0 = blockIdx.x * 24;
    for (int idx = tid; idx < 24 * 16; idx += 240) {
        int r = idx >> 4, q = idx & 15;
        int grow = row0 + r;
        float4 v = make_float4(0.f, 0.f, 0.f, 0.f);
        if (grow < n) {
            v = ((const float4*)g_agg)[grow * 16 + q];
            float4 bb = ((const float4*)b1)[q];
            v.x = fmaxf(v.x + bb.x, 0.f);
            v.y = fmaxf(v.y + bb.y, 0.f);
            v.z = fmaxf(v.z + bb.z, 0.f);
            v.w = fmaxf(v.w + bb.w, 0.f);
        }
        *(float4*)(hs + r * 68 + q * 4) = v;
    }
    __syncthreads();

    float4 acc = make_float4(0.f, 0.f, 0.f, 0.f);
    #pragma unroll
    for (int j = 0; j < 64; j++) {
        float h = hs[ty * 68 + j];
        float4 w = *(const float4*)(Wt + j * 40 + tx * 4);
        acc.x += h * w.x;
        acc.y += h * w.y;
        acc.z += h * w.z;
        acc.w += h * w.w;
    }

    int grow = row0 + ty;
    if (grow < n) {
        float4 bb = *(const float4*)(bfs + tx * 4);
        acc.x += bb.x; acc.y += bb.y; acc.z += bb.z; acc.w += bb.w;
        *(float4*)(out + (size_t)grow * OUTDIM + tx * 4) = acc;
    }
}

// ---------------------------------------------------------------------------
extern "C" void kernel_launch(void* const* d_in, const int* in_sizes, int n_in,
                              void* d_out, int out_size)
{
    const float* X     = (const float*)d_in[0];
    const int*   edges = (const int*)d_in[1];     // int64 downcast to int32 by harness
    const float* W1    = (const float*)d_in[2];
    const float* b1    = (const float*)d_in[3];
    const float* Wfc   = (const float*)d_in[4];
    const float* bfc   = (const float*)d_in[5];
    float* out = (float*)d_out;

    const int n = in_sizes[0] / INDIM;
    const int E = in_sizes[1] / 2;
    const int* src = edges;
    const int* dst = edges + E;

    init_deg_kernel<<<(n + 255) / 256, 256>>>(n);
    deg_accum_kernel<<<(E + 255) / 256, 256>>>(dst, E, n);
    gemm1_mma_kernel<<<(n + 127) / 128, 256>>>(X, W1, n);
    scatter_kernel<<<(E * 4 + 255) / 256, 256>>>(src, dst, E, n);
    gemm2_kernel<<<(n + 23) / 24, dim3(10, 24)>>>(b1, Wfc, bfc, out, n);
}

// round 12
// speedup vs baseline: 1.0578x; 1.0578x over previous
#include <cuda_runtime.h>
#include <cstdint>

#define N_NODES 50000
#define HIDDEN  64
#define INDIM   512
#define OUTDIM  40

// Scratch (device globals)
__device__ __align__(16) float g_hs[N_NODES * HIDDEN];    // dinv[i] * h[i]
__device__ __align__(16) float g_agg[N_NODES * HIDDEN];   // aggregated messages
__device__ __align__(16) float g_deg[N_NODES];
__device__ __align__(16) float g_dinv[N_NODES];

// ---------------------------------------------------------------------------
// Degree: deg[i] = 1 (self loop) + #edges with dst==i
// ---------------------------------------------------------------------------
__global__ void init_deg_kernel(int n) {
    int i = blockIdx.x * blockDim.x + threadIdx.x;
    if (i < n) g_deg[i] = 1.0f;
}

__global__ void deg_accum_kernel(const int* __restrict__ dst, int E, int n) {
    int e = blockIdx.x * blockDim.x + threadIdx.x;
    if (e < E) {
        int d = dst[e];
        if ((unsigned)d < (unsigned)n) atomicAdd(&g_deg[d], 1.0f);
    }
}

// ---------------------------------------------------------------------------
// GEMM1 (tensor cores, tf32): h[n,64] = X[n,512] @ W1[512,64]
// Fused epilogue: d = rsqrt(deg[row]); hs = d*h; agg = d*hs; dinv[row] = d.
// ---------------------------------------------------------------------------
__device__ __forceinline__ uint32_t f2tf32(float f) {
    uint32_t r;
    asm("cvt.rna.tf32.f32 %0, %1;" : "=r"(r) : "f"(f));
    return r;
}

#define XS_STRIDE 36
#define WS_STRIDE 72

__global__ __launch_bounds__(256) void gemm1_mma_kernel(
    const float* __restrict__ X, const float* __restrict__ W, int n)
{
    __shared__ uint32_t Xs[128 * XS_STRIDE];
    __shared__ uint32_t Ws[32 * WS_STRIDE];

    const int tid  = threadIdx.x;
    const int lane = tid & 31;
    const int wid  = tid >> 5;
    const int gid  = lane >> 2;
    const int tig  = lane & 3;
    const int wrow = wid * 16;
    const int row0 = blockIdx.x * 128;

    float acc[8][4] = {};

    for (int k0 = 0; k0 < INDIM; k0 += 32) {
        #pragma unroll
        for (int t = 0; t < 4; t++) {
            int s = t * 256 + tid;
            int r = s >> 3, q = s & 7;
            int rr = row0 + r; if (rr >= n) rr = n - 1;
            float4 v = *(const float4*)(X + (size_t)rr * INDIM + k0 + q * 4);
            uint4 u = make_uint4(f2tf32(v.x), f2tf32(v.y), f2tf32(v.z), f2tf32(v.w));
            *(uint4*)(Xs + r * XS_STRIDE + q * 4) = u;
        }
        #pragma unroll
        for (int t = 0; t < 2; t++) {
            int s = t * 256 + tid;
            int kk = s >> 4, q = s & 15;
            float4 v = *(const float4*)(W + (size_t)(k0 + kk) * HIDDEN + q * 4);
            uint4 u = make_uint4(f2tf32(v.x), f2tf32(v.y), f2tf32(v.z), f2tf32(v.w));
            *(uint4*)(Ws + kk * WS_STRIDE + q * 4) = u;
        }
        __syncthreads();

        #pragma unroll
        for (int kk = 0; kk < 32; kk += 8) {
            uint32_t a0 = Xs[(wrow + gid) * XS_STRIDE + kk + tig];
            uint32_t a1 = Xs[(wrow + gid + 8) * XS_STRIDE + kk + tig];
            uint32_t a2 = Xs[(wrow + gid) * XS_STRIDE + kk + tig + 4];
            uint32_t a3 = Xs[(wrow + gid + 8) * XS_STRIDE + kk + tig + 4];
            #pragma unroll
            for (int nb = 0; nb < 8; nb++) {
                uint32_t b0 = Ws[(kk + tig) * WS_STRIDE + nb * 8 + gid];
                uint32_t b1 = Ws[(kk + tig + 4) * WS_STRIDE + nb * 8 + gid];
                asm volatile(
                    "mma.sync.aligned.m16n8k8.row.col.f32.tf32.tf32.f32 "
                    "{%0,%1,%2,%3}, {%4,%5,%6,%7}, {%8,%9}, {%0,%1,%2,%3};"
                    : "+f"(acc[nb][0]), "+f"(acc[nb][1]),
                      "+f"(acc[nb][2]), "+f"(acc[nb][3])
                    : "r"(a0), "r"(a1), "r"(a2), "r"(a3), "r"(b0), "r"(b1));
            }
        }
        __syncthreads();
    }

    // Fused epilogue
    const int rA = row0 + wrow + gid;
    const int rB = rA + 8;
    float dA = (rA < n) ? rsqrtf(g_deg[rA]) : 0.f;
    float dB = (rB < n) ? rsqrtf(g_deg[rB]) : 0.f;
    if (tig == 0) {
        if (rA < n) g_dinv[rA] = dA;
        if (rB < n) g_dinv[rB] = dB;
    }
    #pragma unroll
    for (int nb = 0; nb < 8; nb++) {
        int col = nb * 8 + 2 * tig;
        if (rA < n) {
            float h0 = dA * acc[nb][0], h1 = dA * acc[nb][1];
            *(float2*)(g_hs  + (size_t)rA * HIDDEN + col) = make_float2(h0, h1);
            *(float2*)(g_agg + (size_t)rA * HIDDEN + col) =
                make_float2(dA * h0, dA * h1);
        }
        if (rB < n) {
            float h2 = dB * acc[nb][2], h3 = dB * acc[nb][3];
            *(float2*)(g_hs  + (size_t)rB * HIDDEN + col) = make_float2(h2, h3);
            *(float2*)(g_agg + (size_t)rB * HIDDEN + col) =
                make_float2(dB * h2, dB * h3);
        }
    }
}

// ---------------------------------------------------------------------------
// Edge scatter: agg[dst,:] += dinv[dst] * hs[src,:]
// 8-thread groups, 2 edges per thread: 4 independent full-line gathers
// + 4 independent v4 reductions per thread (4x MLP, full coalescing).
// ---------------------------------------------------------------------------
__device__ __forceinline__ void red_add_v4(float* addr, float4 v) {
    asm volatile("red.global.add.v4.f32 [%0], {%1, %2, %3, %4};"
                 :: "l"(__cvta_generic_to_global(addr)),
                    "f"(v.x), "f"(v.y), "f"(v.z), "f"(v.w)
                 : "memory");
}

__device__ __forceinline__ float4 scale4(float4 v, float c) {
    return make_float4(c * v.x, c * v.y, c * v.z, c * v.w);
}

__global__ __launch_bounds__(256) void scatter_kernel(
    const int* __restrict__ src, const int* __restrict__ dst, int E, int n)
{
    int idx = blockIdx.x * blockDim.x + threadIdx.x;
    int g = idx >> 3, q = idx & 7;        // group of 8 threads owns edges 2g, 2g+1
    int e0 = 2 * g, e1 = 2 * g + 1;
    if (e0 >= E) return;
    bool has1 = (e1 < E);

    int2 ss = *(const int2*)(src + e0);   // e0 even -> 8B aligned
    int2 dd = *(const int2*)(dst + e0);

    bool ok0 = (unsigned)ss.x < (unsigned)n && (unsigned)dd.x < (unsigned)n;
    bool ok1 = has1 && (unsigned)ss.y < (unsigned)n && (unsigned)dd.y < (unsigned)n;

    if (ok0 && ok1) {
        float c0 = g_dinv[dd.x];
        float c1 = g_dinv[dd.y];
        const float4* h0 = (const float4*)g_hs + ss.x * 16;
        const float4* h1 = (const float4*)g_hs + ss.y * 16;
        // 4 independent gathers
        float4 v00 = __ldg(h0 + q);
        float4 v01 = __ldg(h0 + q + 8);
        float4 v10 = __ldg(h1 + q);
        float4 v11 = __ldg(h1 + q + 8);
        float* b0 = g_agg + (size_t)dd.x * HIDDEN;
        float* b1 = g_agg + (size_t)dd.y * HIDDEN;
        red_add_v4(b0 + q * 4, scale4(v00, c0));
        red_add_v4(b0 + (q + 8) * 4, scale4(v01, c0));
        red_add_v4(b1 + q * 4, scale4(v10, c1));
        red_add_v4(b1 + (q + 8) * 4, scale4(v11, c1));
    } else if (ok0) {
        float c0 = g_dinv[dd.x];
        const float4* h0 = (const float4*)g_hs + ss.x * 16;
        float4 v00 = __ldg(h0 + q);
        float4 v01 = __ldg(h0 + q + 8);
        float* b0 = g_agg + (size_t)dd.x * HIDDEN;
        red_add_v4(b0 + q * 4, scale4(v00, c0));
        red_add_v4(b0 + (q + 8) * 4, scale4(v01, c0));
    } else if (ok1) {
        float c1 = g_dinv[dd.y];
        const float4* h1 = (const float4*)g_hs + ss.y * 16;
        float4 v10 = __ldg(h1 + q);
        float4 v11 = __ldg(h1 + q + 8);
        float* b1 = g_agg + (size_t)dd.y * HIDDEN;
        red_add_v4(b1 + q * 4, scale4(v10, c1));
        red_add_v4(b1 + (q + 8) * 4, scale4(v11, c1));
    }
}

// ---------------------------------------------------------------------------
// GEMM2: out[n,40] = relu(agg + b1) @ Wfc^T + bfc
// ---------------------------------------------------------------------------
__global__ __launch_bounds__(240) void gemm2_kernel(
    const float* __restrict__ b1, const float* __restrict__ Wfc,
    const float* __restrict__ bfc, float* __restrict__ out, int n)
{
    __shared__ float hs[24 * 68];
    __shared__ float Wt[64 * 40];
    __shared__ float bfs[40];

    const int tx = threadIdx.x;     // 0..9
    const int ty = threadIdx.y;     // 0..23
    const int tid = ty * 10 + tx;

    for (int idx = tid; idx < 64 * 40; idx += 240) {
        int o = idx % 40, j = idx / 40;
        Wt[j * 40 + o] = Wfc[o * 64 + j];
    }
    if (tid < 40) bfs[tid] = bfc[tid];

    const int row0 = blockIdx.x * 24;
    for (int idx = tid; idx < 24 * 16; idx += 240) {
        int r = idx >> 4, q = idx & 15;
        int grow = row0 + r;
        float4 v = make_float4(0.f, 0.f, 0.f, 0.f);
        if (grow < n) {
            v = ((const float4*)g_agg)[grow * 16 + q];
            float4 bb = ((const float4*)b1)[q];
            v.x = fmaxf(v.x + bb.x, 0.f);
            v.y = fmaxf(v.y + bb.y, 0.f);
            v.z = fmaxf(v.z + bb.z, 0.f);
            v.w = fmaxf(v.w + bb.w, 0.f);
        }
        *(float4*)(hs + r * 68 + q * 4) = v;
    }
    __syncthreads();

    float4 acc = make_float4(0.f, 0.f, 0.f, 0.f);
    #pragma unroll
    for (int j = 0; j < 64; j++) {
        float h = hs[ty * 68 + j];
        float4 w = *(const float4*)(Wt + j * 40 + tx * 4);
        acc.x += h * w.x;
        acc.y += h * w.y;
        acc.z += h * w.z;
        acc.w += h * w.w;
    }

    int grow = row0 + ty;
    if (grow < n) {
        float4 bb = *(const float4*)(bfs + tx * 4);
        acc.x += bb.x; acc.y += bb.y; acc.z += bb.z; acc.w += bb.w;
        *(float4*)(out + (size_t)grow * OUTDIM + tx * 4) = acc;
    }
}

// ---------------------------------------------------------------------------
extern "C" void kernel_launch(void* const* d_in, const int* in_sizes, int n_in,
                              void* d_out, int out_size)
{
    const float* X     = (const float*)d_in[0];
    const int*   edges = (const int*)d_in[1];     // int64 downcast to int32 by harness
    const float* W1    = (const float*)d_in[2];
    const float* b1    = (const float*)d_in[3];
    const float* Wfc   = (const float*)d_in[4];
    const float* bfc   = (const float*)d_in[5];
    float* out = (float*)d_out;

    const int n = in_sizes[0] / INDIM;
    const int E = in_sizes[1] / 2;
    const int* src = edges;
    const int* dst = edges + E;

    init_deg_kernel<<<(n + 255) / 256, 256>>>(n);
    deg_accum_kernel<<<(E + 255) / 256, 256>>>(dst, E, n);
    gemm1_mma_kernel<<<(n + 127) / 128, 256>>>(X, W1, n);
    int groups = (E + 1) / 2;
    scatter_kernel<<<(groups * 8 + 255) / 256, 256>>>(src, dst, E, n);
    gemm2_kernel<<<(n + 23) / 24, dim3(10, 24)>>>(b1, Wfc, bfc, out, n);
}

// round 13
// speedup vs baseline: 1.0773x; 1.0184x over previous
#include <cuda_runtime.h>
#include <cstdint>

#define N_NODES 50000
#define HIDDEN  64
#define INDIM   512
#define OUTDIM  40

// Scratch (device globals)
__device__ __align__(16) float g_hs[N_NODES * HIDDEN];    // dinv[i] * h[i]
__device__ __align__(16) float g_agg[N_NODES * HIDDEN];   // raw sums (pre-dinv[dst])
__device__ __align__(16) float g_deg[N_NODES];
__device__ __align__(16) float g_dinv[N_NODES];

// ---------------------------------------------------------------------------
// Degree: deg[i] = 1 (self loop) + #edges with dst==i
// ---------------------------------------------------------------------------
__global__ void init_deg_kernel(int n) {
    int i = blockIdx.x * blockDim.x + threadIdx.x;
    if (i < n) g_deg[i] = 1.0f;
}

__global__ void deg_accum_kernel(const int* __restrict__ dst, int E, int n) {
    int e = blockIdx.x * blockDim.x + threadIdx.x;
    if (e < E) {
        int d = dst[e];
        if ((unsigned)d < (unsigned)n) atomicAdd(&g_deg[d], 1.0f);
    }
}

// ---------------------------------------------------------------------------
// GEMM1 (tensor cores, tf32): h[n,64] = X[n,512] @ W1[512,64]
// Fused epilogue: d = rsqrt(deg[row]); hs = d*h; agg_raw = hs; dinv[row] = d.
// ---------------------------------------------------------------------------
__device__ __forceinline__ uint32_t f2tf32(float f) {
    uint32_t r;
    asm("cvt.rna.tf32.f32 %0, %1;" : "=r"(r) : "f"(f));
    return r;
}

#define XS_STRIDE 36
#define WS_STRIDE 72

__global__ __launch_bounds__(256) void gemm1_mma_kernel(
    const float* __restrict__ X, const float* __restrict__ W, int n)
{
    __shared__ uint32_t Xs[128 * XS_STRIDE];
    __shared__ uint32_t Ws[32 * WS_STRIDE];

    const int tid  = threadIdx.x;
    const int lane = tid & 31;
    const int wid  = tid >> 5;
    const int gid  = lane >> 2;
    const int tig  = lane & 3;
    const int wrow = wid * 16;
    const int row0 = blockIdx.x * 128;

    float acc[8][4] = {};

    for (int k0 = 0; k0 < INDIM; k0 += 32) {
        #pragma unroll
        for (int t = 0; t < 4; t++) {
            int s = t * 256 + tid;
            int r = s >> 3, q = s & 7;
            int rr = row0 + r; if (rr >= n) rr = n - 1;
            float4 v = *(const float4*)(X + (size_t)rr * INDIM + k0 + q * 4);
            uint4 u = make_uint4(f2tf32(v.x), f2tf32(v.y), f2tf32(v.z), f2tf32(v.w));
            *(uint4*)(Xs + r * XS_STRIDE + q * 4) = u;
        }
        #pragma unroll
        for (int t = 0; t < 2; t++) {
            int s = t * 256 + tid;
            int kk = s >> 4, q = s & 15;
            float4 v = *(const float4*)(W + (size_t)(k0 + kk) * HIDDEN + q * 4);
            uint4 u = make_uint4(f2tf32(v.x), f2tf32(v.y), f2tf32(v.z), f2tf32(v.w));
            *(uint4*)(Ws + kk * WS_STRIDE + q * 4) = u;
        }
        __syncthreads();

        #pragma unroll
        for (int kk = 0; kk < 32; kk += 8) {
            uint32_t a0 = Xs[(wrow + gid) * XS_STRIDE + kk + tig];
            uint32_t a1 = Xs[(wrow + gid + 8) * XS_STRIDE + kk + tig];
            uint32_t a2 = Xs[(wrow + gid) * XS_STRIDE + kk + tig + 4];
            uint32_t a3 = Xs[(wrow + gid + 8) * XS_STRIDE + kk + tig + 4];
            #pragma unroll
            for (int nb = 0; nb < 8; nb++) {
                uint32_t b0 = Ws[(kk + tig) * WS_STRIDE + nb * 8 + gid];
                uint32_t b1 = Ws[(kk + tig + 4) * WS_STRIDE + nb * 8 + gid];
                asm volatile(
                    "mma.sync.aligned.m16n8k8.row.col.f32.tf32.tf32.f32 "
                    "{%0,%1,%2,%3}, {%4,%5,%6,%7}, {%8,%9}, {%0,%1,%2,%3};"
                    : "+f"(acc[nb][0]), "+f"(acc[nb][1]),
                      "+f"(acc[nb][2]), "+f"(acc[nb][3])
                    : "r"(a0), "r"(a1), "r"(a2), "r"(a3), "r"(b0), "r"(b1));
            }
        }
        __syncthreads();
    }

    // Fused epilogue: hs = d*h; agg_raw = hs (self-loop term, dinv[dst] deferred)
    const int rA = row0 + wrow + gid;
    const int rB = rA + 8;
    float dA = (rA < n) ? rsqrtf(g_deg[rA]) : 0.f;
    float dB = (rB < n) ? rsqrtf(g_deg[rB]) : 0.f;
    if (tig == 0) {
        if (rA < n) g_dinv[rA] = dA;
        if (rB < n) g_dinv[rB] = dB;
    }
    #pragma unroll
    for (int nb = 0; nb < 8; nb++) {
        int col = nb * 8 + 2 * tig;
        if (rA < n) {
            float2 h01 = make_float2(dA * acc[nb][0], dA * acc[nb][1]);
            *(float2*)(g_hs  + (size_t)rA * HIDDEN + col) = h01;
            *(float2*)(g_agg + (size_t)rA * HIDDEN + col) = h01;
        }
        if (rB < n) {
            float2 h23 = make_float2(dB * acc[nb][2], dB * acc[nb][3]);
            *(float2*)(g_hs  + (size_t)rB * HIDDEN + col) = h23;
            *(float2*)(g_agg + (size_t)rB * HIDDEN + col) = h23;
        }
    }
}

// ---------------------------------------------------------------------------
// Edge scatter: agg_raw[dst,:] += hs[src,:]  (pure gather + reduction)
// 8-thread groups, 2 edges per thread: 4 independent full-line gathers
// + 4 independent v4 reductions per thread.
// ---------------------------------------------------------------------------
__device__ __forceinline__ void red_add_v4(float* addr, float4 v) {
    asm volatile("red.global.add.v4.f32 [%0], {%1, %2, %3, %4};"
                 :: "l"(__cvta_generic_to_global(addr)),
                    "f"(v.x), "f"(v.y), "f"(v.z), "f"(v.w)
                 : "memory");
}

__global__ __launch_bounds__(256) void scatter_kernel(
    const int* __restrict__ src, const int* __restrict__ dst, int E, int n)
{
    int idx = blockIdx.x * blockDim.x + threadIdx.x;
    int g = idx >> 3, q = idx & 7;        // group of 8 threads owns edges 2g, 2g+1
    int e0 = 2 * g, e1 = 2 * g + 1;
    if (e0 >= E) return;
    bool has1 = (e1 < E);

    int2 ss = *(const int2*)(src + e0);   // e0 even -> 8B aligned
    int2 dd = *(const int2*)(dst + e0);

    bool ok0 = (unsigned)ss.x < (unsigned)n && (unsigned)dd.x < (unsigned)n;
    bool ok1 = has1 && (unsigned)ss.y < (unsigned)n && (unsigned)dd.y < (unsigned)n;

    if (ok0 && ok1) {
        const float4* h0 = (const float4*)g_hs + ss.x * 16;
        const float4* h1 = (const float4*)g_hs + ss.y * 16;
        float4 v00 = __ldg(h0 + q);
        float4 v01 = __ldg(h0 + q + 8);
        float4 v10 = __ldg(h1 + q);
        float4 v11 = __ldg(h1 + q + 8);
        float* b0 = g_agg + (size_t)dd.x * HIDDEN;
        float* b1 = g_agg + (size_t)dd.y * HIDDEN;
        red_add_v4(b0 + q * 4, v00);
        red_add_v4(b0 + (q + 8) * 4, v01);
        red_add_v4(b1 + q * 4, v10);
        red_add_v4(b1 + (q + 8) * 4, v11);
    } else if (ok0) {
        const float4* h0 = (const float4*)g_hs + ss.x * 16;
        float4 v00 = __ldg(h0 + q);
        float4 v01 = __ldg(h0 + q + 8);
        float* b0 = g_agg + (size_t)dd.x * HIDDEN;
        red_add_v4(b0 + q * 4, v00);
        red_add_v4(b0 + (q + 8) * 4, v01);
    } else if (ok1) {
        const float4* h1 = (const float4*)g_hs + ss.y * 16;
        float4 v10 = __ldg(h1 + q);
        float4 v11 = __ldg(h1 + q + 8);
        float* b1 = g_agg + (size_t)dd.y * HIDDEN;
        red_add_v4(b1 + q * 4, v10);
        red_add_v4(b1 + (q + 8) * 4, v11);
    }
}

// ---------------------------------------------------------------------------
// GEMM2: out[n,40] = relu(dinv[row]*agg_raw + b1) @ Wfc^T + bfc
// ---------------------------------------------------------------------------
__global__ __launch_bounds__(240) void gemm2_kernel(
    const float* __restrict__ b1, const float* __restrict__ Wfc,
    const float* __restrict__ bfc, float* __restrict__ out, int n)
{
    __shared__ float hs[24 * 68];
    __shared__ float Wt[64 * 40];
    __shared__ float bfs[40];

    const int tx = threadIdx.x;     // 0..9
    const int ty = threadIdx.y;     // 0..23
    const int tid = ty * 10 + tx;

    for (int idx = tid; idx < 64 * 40; idx += 240) {
        int o = idx % 40, j = idx / 40;
        Wt[j * 40 + o] = Wfc[o * 64 + j];
    }
    if (tid < 40) bfs[tid] = bfc[tid];

    const int row0 = blockIdx.x * 24;
    for (int idx = tid; idx < 24 * 16; idx += 240) {
        int r = idx >> 4, q = idx & 15;
        int grow = row0 + r;
        float4 v = make_float4(0.f, 0.f, 0.f, 0.f);
        if (grow < n) {
            float dv = g_dinv[grow];
            v = ((const float4*)g_agg)[grow * 16 + q];
            float4 bb = ((const float4*)b1)[q];
            v.x = fmaxf(fmaf(dv, v.x, bb.x), 0.f);
            v.y = fmaxf(fmaf(dv, v.y, bb.y), 0.f);
            v.z = fmaxf(fmaf(dv, v.z, bb.z), 0.f);
            v.w = fmaxf(fmaf(dv, v.w, bb.w), 0.f);
        }
        *(float4*)(hs + r * 68 + q * 4) = v;
    }
    __syncthreads();

    float4 acc = make_float4(0.f, 0.f, 0.f, 0.f);
    #pragma unroll
    for (int j = 0; j < 64; j++) {
        float h = hs[ty * 68 + j];
        float4 w = *(const float4*)(Wt + j * 40 + tx * 4);
        acc.x += h * w.x;
        acc.y += h * w.y;
        acc.z += h * w.z;
        acc.w += h * w.w;
    }

    int grow = row0 + ty;
    if (grow < n) {
        float4 bb = *(const float4*)(bfs + tx * 4);
        acc.x += bb.x; acc.y += bb.y; acc.z += bb.z; acc.w += bb.w;
        *(float4*)(out + (size_t)grow * OUTDIM + tx * 4) = acc;
    }
}

// ---------------------------------------------------------------------------
extern "C" void kernel_launch(void* const* d_in, const int* in_sizes, int n_in,
                              void* d_out, int out_size)
{
    const float* X     = (const float*)d_in[0];
    const int*   edges = (const int*)d_in[1];     // int64 downcast to int32 by harness
    const float* W1    = (const float*)d_in[2];
    const float* b1    = (const float*)d_in[3];
    const float* Wfc   = (const float*)d_in[4];
    const float* bfc   = (const float*)d_in[5];
    float* out = (float*)d_out;

    const int n = in_sizes[0] / INDIM;
    const int E = in_sizes[1] / 2;
    const int* src = edges;
    const int* dst = edges + E;

    init_deg_kernel<<<(n + 255) / 256, 256>>>(n);
    deg_accum_kernel<<<(E + 255) / 256, 256>>>(dst, E, n);
    gemm1_mma_kernel<<<(n + 127) / 128, 256>>>(X, W1, n);
    int groups = (E + 1) / 2;
    scatter_kernel<<<(groups * 8 + 255) / 256, 256>>>(src, dst, E, n);
    gemm2_kernel<<<(n + 23) / 24, dim3(10, 24)>>>(b1, Wfc, bfc, out, n);
}